// round 11
// baseline (speedup 1.0000x reference)
#include <cuda_runtime.h>
#include <cuda_fp16.h>

#define NMAX 100000
#define EMAX 1600000
#define F1 128
#define F2 64
#define BN_EPS 1e-5f
#define SCAN_B 1024
#define BN_GRID 1024

// ---- scratch (device globals; zero-initialized at load; no allocation) ----
__device__ float  g_dis[NMAX];             // rsqrt(degree)
__device__ int    g_degi[NMAX];            // in-degree (zeroed by agg2 restore)
__device__ int    g_row[NMAX];             // CSR row start
__device__ int    g_epos[EMAX];            // per-edge rank within destination
__device__ int    g_pub[128];              // scan block totals+1 (zero-restored)
__device__ int    g_csr[EMAX];             // src indices grouped by dst
__device__ uint4  g_H1h[NMAX * 16];        // fp16 dis*(x@W1^T)        [N,128]
__device__ uint4  g_A1h[NMAX * 16];        // fp16 layer-1 aggregated  [N,128]
__device__ uint4  g_H2h[NMAX * 8];         // fp16 dis*(relu(bn)@W2^T) [N,64]
__device__ float  g_sums[2 * F1];          // BN sum/sumsq (zero-restored)
__device__ uint4  g_W1h4[F1 * F1 / 8];     // fp16 W1 row-major [c][k]
__device__ uint4  g_W2h4[F1 * F2 / 8];     // fp16 W2 row-major [c][k]

// ---- fp16 mma m16n8k16 (row.col, f32 accum) ----
__device__ __forceinline__ void mma_f16(float* d, const unsigned* a, const unsigned* b) {
    asm volatile(
        "mma.sync.aligned.m16n8k16.row.col.f32.f16.f16.f32 "
        "{%0,%1,%2,%3}, {%4,%5,%6,%7}, {%8,%9}, {%0,%1,%2,%3};"
        : "+f"(d[0]), "+f"(d[1]), "+f"(d[2]), "+f"(d[3])
        : "r"(a[0]), "r"(a[1]), "r"(a[2]), "r"(a[3]), "r"(b[0]), "r"(b[1]));
}

__device__ __forceinline__ unsigned pack_half2(float a, float b) {
    __half2 h = __floats2half2_rn(a, b);
    return *reinterpret_cast<unsigned*>(&h);
}

// fp16 row accumulate: acc[0..7] += unpack(u)
__device__ __forceinline__ void acc_u4(float* acc, uint4 u) {
    float2 f0 = __half22float2(*(__half2*)&u.x);
    float2 f1 = __half22float2(*(__half2*)&u.y);
    float2 f2 = __half22float2(*(__half2*)&u.z);
    float2 f3 = __half22float2(*(__half2*)&u.w);
    acc[0] += f0.x; acc[1] += f0.y;
    acc[2] += f1.x; acc[3] += f1.y;
    acc[4] += f2.x; acc[5] += f2.y;
    acc[6] += f3.x; acc[7] += f3.y;
}

// ---------------------------------------------------------------------------
// degree count + per-edge rank; also converts weights to fp16 (no ordering
// hazard: weights consumed only by later gemm kernels)
// ---------------------------------------------------------------------------
__global__ void k_deg_count(const int* __restrict__ ei,
                            const float* __restrict__ W1,
                            const float* __restrict__ W2, int e_cnt) {
    int e = blockIdx.x * blockDim.x + threadIdx.x;
    if (e < F1 * F1) ((__half*)g_W1h4)[e] = __float2half_rn(W1[e]);
    if (e < F1 * F2) ((__half*)g_W2h4)[e] = __float2half_rn(W2[e]);
    if (e < e_cnt) {
        int d = ei[e_cnt + e];
        g_epos[e] = atomicAdd(&g_degi[d], 1);
    }
}

// ---------------------------------------------------------------------------
// single-pass scan (publish + lookback); all <=98 blocks co-resident
// ---------------------------------------------------------------------------
__global__ void __launch_bounds__(SCAN_B) k_scan(int n) {
    __shared__ int wtot[32];
    __shared__ int red[32];
    int t = threadIdx.x, b = blockIdx.x;
    int lane = t & 31, wid = t >> 5;
    int i = b * SCAN_B + t;
    int v = (i < n) ? g_degi[i] : 0;

    // warp inclusive scan
    int s = v;
    #pragma unroll
    for (int o = 1; o < 32; o <<= 1) {
        int u = __shfl_up_sync(0xffffffffu, s, o);
        if (lane >= o) s += u;
    }
    if (lane == 31) wtot[wid] = s;
    __syncthreads();
    if (wid == 0) {
        int ws = wtot[lane];
        #pragma unroll
        for (int o = 1; o < 32; o <<= 1) {
            int u = __shfl_up_sync(0xffffffffu, ws, o);
            if (lane >= o) ws += u;
        }
        wtot[lane] = ws;
    }
    __syncthreads();
    int incl = s + (wid ? wtot[wid - 1] : 0);
    int T = wtot[31];

    // publish own total (flag = T+1), then look back at lower blocks
    if (t == 0) atomicExch(&g_pub[b], T + 1);
    int part = 0;
    if (t < b) {
        volatile int* p = &g_pub[t];
        int x;
        while ((x = *p) == 0) {}
        part = x - 1;
    }
    #pragma unroll
    for (int o = 16; o; o >>= 1) part += __shfl_down_sync(0xffffffffu, part, o);
    if (lane == 0) red[wid] = part;
    __syncthreads();
    if (t < 32) {
        int z = red[t];
        #pragma unroll
        for (int o = 16; o; o >>= 1) z += __shfl_down_sync(0xffffffffu, z, o);
        if (t == 0) red[0] = z;
    }
    __syncthreads();
    int off = red[0];

    if (i < n) {
        g_row[i] = incl - v + off;          // global exclusive prefix
        g_dis[i] = rsqrtf((float)(v + 1));  // +1 self-loop
    }
}

// atomic-free CSR fill using precomputed ranks
__global__ void k_csr_fill(const int* __restrict__ ei, int e_cnt) {
    int e = blockIdx.x * blockDim.x + threadIdx.x;
    if (e < e_cnt) {
        int s = ei[e];
        int d = ei[e_cnt + e];
        g_csr[g_row[d] + g_epos[e]] = s;
    }
}

// ---------------------------------------------------------------------------
// GEMM1 (fp16 mma): H1h = fp16(dis .* (x @ W1^T))
// 256 threads, tile 128x128. Warp w: rows 32*(w>>1), cols 64*(w&1).
// ---------------------------------------------------------------------------
__global__ void __launch_bounds__(256) k_gemm1(const float* __restrict__ x, int n) {
    __shared__ unsigned xs[128][20];
    __shared__ unsigned ws[128][20];
    int t = threadIdx.x;
    int w = t >> 5, lane = t & 31;
    int gid = lane >> 2, tig = lane & 3;
    int rbase = (w >> 1) * 32;
    int cbase = (w & 1) * 64;
    int row0 = blockIdx.x * 128;

    float acc[2][8][4];
    #pragma unroll
    for (int m = 0; m < 2; m++)
        #pragma unroll
        for (int nt = 0; nt < 8; nt++)
            #pragma unroll
            for (int j = 0; j < 4; j++) acc[m][nt][j] = 0.0f;

    for (int kc = 0; kc < F1; kc += 32) {
        for (int i = t; i < 1024; i += 256) {
            int r = i >> 3, kq = i & 7;
            int gr = row0 + r;
            float4 v = make_float4(0.f, 0.f, 0.f, 0.f);
            if (gr < n) v = ((const float4*)x)[gr * 32 + (kc >> 2) + kq];
            xs[r][kq * 2]     = pack_half2(v.x, v.y);
            xs[r][kq * 2 + 1] = pack_half2(v.z, v.w);
        }
        for (int i = t; i < 512; i += 256) {
            int c = i >> 2, q = i & 3;
            *(uint4*)&ws[c][q * 4] = g_W1h4[c * 16 + (kc >> 3) + q];
        }
        __syncthreads();

        #pragma unroll
        for (int ks2 = 0; ks2 < 16; ks2 += 8) {
            unsigned a[2][4], b[8][2];
            #pragma unroll
            for (int m = 0; m < 2; m++) {
                int r0 = rbase + 16 * m + gid;
                a[m][0] = xs[r0][ks2 + tig];
                a[m][1] = xs[r0 + 8][ks2 + tig];
                a[m][2] = xs[r0][ks2 + tig + 4];
                a[m][3] = xs[r0 + 8][ks2 + tig + 4];
            }
            #pragma unroll
            for (int nt = 0; nt < 8; nt++) {
                int c = cbase + 8 * nt + gid;
                b[nt][0] = ws[c][ks2 + tig];
                b[nt][1] = ws[c][ks2 + tig + 4];
            }
            #pragma unroll
            for (int m = 0; m < 2; m++)
                #pragma unroll
                for (int nt = 0; nt < 8; nt++)
                    mma_f16(acc[m][nt], a[m], b[nt]);
        }
        __syncthreads();
    }

    __half2* H1 = (__half2*)g_H1h;
    #pragma unroll
    for (int m = 0; m < 2; m++) {
        int r_lo = row0 + rbase + 16 * m + gid;
        int r_hi = r_lo + 8;
        float dlo = (r_lo < n) ? g_dis[r_lo] : 0.0f;
        float dhi = (r_hi < n) ? g_dis[r_hi] : 0.0f;
        #pragma unroll
        for (int nt = 0; nt < 8; nt++) {
            int c = cbase + 8 * nt + 2 * tig;
            if (r_lo < n)
                H1[r_lo * 64 + (c >> 1)] =
                    __floats2half2_rn(acc[m][nt][0] * dlo, acc[m][nt][1] * dlo);
            if (r_hi < n)
                H1[r_hi * 64 + (c >> 1)] =
                    __floats2half2_rn(acc[m][nt][2] * dhi, acc[m][nt][3] * dhi);
        }
    }
}

// ---------------------------------------------------------------------------
// layer-1 pull aggregation: half-warp (16 lanes) per node, fp16 gather,
// fp32 accumulate, fp16 store. agg[i] = dis[i]*(H1[i] + sum_s H1[s]) + b1
// ---------------------------------------------------------------------------
__global__ void __launch_bounds__(256) k_agg1(const float* __restrict__ b1, int n) {
    int t = threadIdx.x;
    int i = blockIdx.x * 16 + (t >> 4);
    int q = t & 15;                    // 16B chunk = 8 halfs = cols 8q..8q+7
    if (i >= n) return;
    int start = g_row[i];
    int deg   = g_degi[i];
    int endj  = start + deg;
    float acc[8] = {0, 0, 0, 0, 0, 0, 0, 0};
    acc_u4(acc, g_H1h[i * 16 + q]);    // self-loop
    int j = start;
    for (; j + 3 < endj; j += 4) {
        int s0 = __ldg(&g_csr[j]),     s1 = __ldg(&g_csr[j + 1]);
        int s2 = __ldg(&g_csr[j + 2]), s3 = __ldg(&g_csr[j + 3]);
        uint4 u0 = g_H1h[s0 * 16 + q];
        uint4 u1 = g_H1h[s1 * 16 + q];
        uint4 u2 = g_H1h[s2 * 16 + q];
        uint4 u3 = g_H1h[s3 * 16 + q];
        acc_u4(acc, u0); acc_u4(acc, u1); acc_u4(acc, u2); acc_u4(acc, u3);
    }
    for (; j < endj; j++) acc_u4(acc, g_H1h[__ldg(&g_csr[j]) * 16 + q]);

    float di = g_dis[i];
    float4 b0 = ((const float4*)b1)[2 * q];
    float4 b1v = ((const float4*)b1)[2 * q + 1];
    uint4 o;
    o.x = pack_half2(fmaf(acc[0], di, b0.x),  fmaf(acc[1], di, b0.y));
    o.y = pack_half2(fmaf(acc[2], di, b0.z),  fmaf(acc[3], di, b0.w));
    o.z = pack_half2(fmaf(acc[4], di, b1v.x), fmaf(acc[5], di, b1v.y));
    o.w = pack_half2(fmaf(acc[6], di, b1v.z), fmaf(acc[7], di, b1v.w));
    g_A1h[i * 16 + q] = o;
}

// ---------------------------------------------------------------------------
// BN statistics over fp16 AGG1 (L2-resident), 4-deep MLP
// ---------------------------------------------------------------------------
__global__ void k_bnstats(int n) {
    const __half* A = (const __half*)g_A1h;
    int c = threadIdx.x;  // 128
    float s = 0.0f, s2 = 0.0f;
    int r = blockIdx.x;
    for (; r + 3 * BN_GRID < n; r += 4 * BN_GRID) {
        float v0 = __half2float(A[(r) * F1 + c]);
        float v1 = __half2float(A[(r + BN_GRID) * F1 + c]);
        float v2 = __half2float(A[(r + 2 * BN_GRID) * F1 + c]);
        float v3 = __half2float(A[(r + 3 * BN_GRID) * F1 + c]);
        s += v0 + v1 + v2 + v3;
        s2 = fmaf(v0, v0, s2); s2 = fmaf(v1, v1, s2);
        s2 = fmaf(v2, v2, s2); s2 = fmaf(v3, v3, s2);
    }
    for (; r < n; r += BN_GRID) {
        float v = __half2float(A[r * F1 + c]);
        s += v;
        s2 = fmaf(v, v, s2);
    }
    atomicAdd(&g_sums[c], s);
    atomicAdd(&g_sums[F1 + c], s2);
}

// ---------------------------------------------------------------------------
// GEMM2 (fp16 mma): H2h = fp16(dis .* (relu(bn(A1h)) @ W2^T))
// BN scale/shift computed per-block in prologue (replaces k_bnfinal).
// ---------------------------------------------------------------------------
__global__ void __launch_bounds__(256) k_gemm2(const float* __restrict__ gamma,
                                               const float* __restrict__ beta, int n) {
    __shared__ unsigned xs[128][20];
    __shared__ unsigned ws[64][20];
    __shared__ float sc_s[F1];
    __shared__ float sh_s[F1];
    int t = threadIdx.x;
    int w = t >> 5, lane = t & 31;
    int gid = lane >> 2, tig = lane & 3;
    int rbase = w * 16;
    int row0 = blockIdx.x * 128;

    if (t < F1) {
        float inv_n = 1.0f / (float)n;
        float mean = g_sums[t] * inv_n;
        float var = g_sums[F1 + t] * inv_n - mean * mean;
        float inv = rsqrtf(var + BN_EPS);
        float sc = gamma[t] * inv;
        sc_s[t] = sc;
        sh_s[t] = beta[t] - mean * sc;
    }
    __syncthreads();

    float acc[8][4];
    #pragma unroll
    for (int nt = 0; nt < 8; nt++)
        #pragma unroll
        for (int j = 0; j < 4; j++) acc[nt][j] = 0.0f;

    for (int kc = 0; kc < F1; kc += 32) {
        // stage bn+relu(A1h) chunk as fp16: 128 rows x 4 uint4
        for (int i = t; i < 512; i += 256) {
            int r = i >> 2, q = i & 3;
            int gr = row0 + r;
            unsigned o0 = 0, o1 = 0, o2 = 0, o3 = 0;
            if (gr < n) {
                uint4 u = g_A1h[gr * 16 + (kc >> 3) + q];
                int f = kc + 8 * q;
                float2 f0 = __half22float2(*(__half2*)&u.x);
                float2 f1 = __half22float2(*(__half2*)&u.y);
                float2 f2 = __half22float2(*(__half2*)&u.z);
                float2 f3 = __half22float2(*(__half2*)&u.w);
                float v0 = fmaxf(fmaf(f0.x, sc_s[f + 0], sh_s[f + 0]), 0.0f);
                float v1 = fmaxf(fmaf(f0.y, sc_s[f + 1], sh_s[f + 1]), 0.0f);
                float v2 = fmaxf(fmaf(f1.x, sc_s[f + 2], sh_s[f + 2]), 0.0f);
                float v3 = fmaxf(fmaf(f1.y, sc_s[f + 3], sh_s[f + 3]), 0.0f);
                float v4 = fmaxf(fmaf(f2.x, sc_s[f + 4], sh_s[f + 4]), 0.0f);
                float v5 = fmaxf(fmaf(f2.y, sc_s[f + 5], sh_s[f + 5]), 0.0f);
                float v6 = fmaxf(fmaf(f3.x, sc_s[f + 6], sh_s[f + 6]), 0.0f);
                float v7 = fmaxf(fmaf(f3.y, sc_s[f + 7], sh_s[f + 7]), 0.0f);
                o0 = pack_half2(v0, v1); o1 = pack_half2(v2, v3);
                o2 = pack_half2(v4, v5); o3 = pack_half2(v6, v7);
            }
            xs[r][q * 4 + 0] = o0; xs[r][q * 4 + 1] = o1;
            xs[r][q * 4 + 2] = o2; xs[r][q * 4 + 3] = o3;
        }
        if (t < 256) {
            int c = t >> 2, q = t & 3;
            *(uint4*)&ws[c][q * 4] = g_W2h4[c * 16 + (kc >> 3) + q];
        }
        __syncthreads();

        #pragma unroll
        for (int ks2 = 0; ks2 < 16; ks2 += 8) {
            unsigned a[4], b[8][2];
            {
                int r0 = rbase + gid;
                a[0] = xs[r0][ks2 + tig];
                a[1] = xs[r0 + 8][ks2 + tig];
                a[2] = xs[r0][ks2 + tig + 4];
                a[3] = xs[r0 + 8][ks2 + tig + 4];
            }
            #pragma unroll
            for (int nt = 0; nt < 8; nt++) {
                int c = 8 * nt + gid;
                b[nt][0] = ws[c][ks2 + tig];
                b[nt][1] = ws[c][ks2 + tig + 4];
            }
            #pragma unroll
            for (int nt = 0; nt < 8; nt++)
                mma_f16(acc[nt], a, b[nt]);
        }
        __syncthreads();
    }

    __half2* H2 = (__half2*)g_H2h;
    int r_lo = row0 + rbase + gid;
    int r_hi = r_lo + 8;
    float dlo = (r_lo < n) ? g_dis[r_lo] : 0.0f;
    float dhi = (r_hi < n) ? g_dis[r_hi] : 0.0f;
    #pragma unroll
    for (int nt = 0; nt < 8; nt++) {
        int c = 8 * nt + 2 * tig;
        if (r_lo < n)
            H2[r_lo * 32 + (c >> 1)] =
                __floats2half2_rn(acc[nt][0] * dlo, acc[nt][1] * dlo);
        if (r_hi < n)
            H2[r_hi * 32 + (c >> 1)] =
                __floats2half2_rn(acc[nt][2] * dhi, acc[nt][3] * dhi);
    }
}

// ---------------------------------------------------------------------------
// layer-2 pull aggregation: quarter-warp (8 lanes) per node, fp16 gather,
// writes d_out fp32 directly. Also restores zeroed state for next replay.
// ---------------------------------------------------------------------------
__global__ void __launch_bounds__(256) k_agg2(const float* __restrict__ b2, int n,
                                              float4* __restrict__ out) {
    int t = threadIdx.x;
    // restore zero state for next graph replay (none of these are read by agg2)
    if (blockIdx.x == 0) {
        if (t < 2 * F1) g_sums[t] = 0.0f;
        if (t < 128) g_pub[t] = 0;
    }
    int i = blockIdx.x * 32 + (t >> 3);
    int q = t & 7;                     // cols 8q..8q+7
    if (i >= n) return;
    int start = g_row[i];
    int deg   = g_degi[i];
    if (q == 0) g_degi[i] = 0;         // restore for next replay (read above)
    int endj  = start + deg;
    float acc[8] = {0, 0, 0, 0, 0, 0, 0, 0};
    acc_u4(acc, g_H2h[i * 8 + q]);     // self-loop
    int j = start;
    for (; j + 3 < endj; j += 4) {
        int s0 = __ldg(&g_csr[j]),     s1 = __ldg(&g_csr[j + 1]);
        int s2 = __ldg(&g_csr[j + 2]), s3 = __ldg(&g_csr[j + 3]);
        uint4 u0 = g_H2h[s0 * 8 + q];
        uint4 u1 = g_H2h[s1 * 8 + q];
        uint4 u2 = g_H2h[s2 * 8 + q];
        uint4 u3 = g_H2h[s3 * 8 + q];
        acc_u4(acc, u0); acc_u4(acc, u1); acc_u4(acc, u2); acc_u4(acc, u3);
    }
    for (; j < endj; j++) acc_u4(acc, g_H2h[__ldg(&g_csr[j]) * 8 + q]);

    float di = g_dis[i];
    float4 b0 = ((const float4*)b2)[2 * q];
    float4 b1v = ((const float4*)b2)[2 * q + 1];
    out[i * 16 + 2 * q] =
        make_float4(fmaf(acc[0], di, b0.x), fmaf(acc[1], di, b0.y),
                    fmaf(acc[2], di, b0.z), fmaf(acc[3], di, b0.w));
    out[i * 16 + 2 * q + 1] =
        make_float4(fmaf(acc[4], di, b1v.x), fmaf(acc[5], di, b1v.y),
                    fmaf(acc[6], di, b1v.z), fmaf(acc[7], di, b1v.w));
}

// ---------------------------------------------------------------------------
extern "C" void kernel_launch(void* const* d_in, const int* in_sizes, int n_in,
                              void* d_out, int out_size) {
    const float* x     = (const float*)d_in[0];
    const int*   ei    = (const int*)d_in[1];
    const float* W1    = (const float*)d_in[2];
    const float* b1    = (const float*)d_in[3];
    const float* gamma = (const float*)d_in[4];
    const float* beta  = (const float*)d_in[5];
    const float* W2    = (const float*)d_in[6];
    const float* b2    = (const float*)d_in[7];

    int n = in_sizes[0] / F1;       // 100000
    int e = in_sizes[1] / 2;        // 1600000
    int nb = (n + SCAN_B - 1) / SCAN_B;   // 98 <= 128 (co-resident)

    // CSR build (degi/g_pub/g_sums arrive zeroed: load-time init + agg2 restore)
    k_deg_count<<<(e + 255) / 256, 256>>>(ei, W1, W2, e);
    k_scan<<<nb, SCAN_B>>>(n);
    k_csr_fill<<<(e + 255) / 256, 256>>>(ei, e);

    // layer 1
    k_gemm1<<<(n + 127) / 128, 256>>>(x, n);
    k_agg1<<<(n + 15) / 16, 256>>>(b1, n);

    // BN stats
    k_bnstats<<<BN_GRID, 128>>>(n);

    // layer 2 (BN finalize folded into gemm2 prologue)
    k_gemm2<<<(n + 127) / 128, 256>>>(gamma, beta, n);
    k_agg2<<<(n + 31) / 32, 256>>>(b2, n, (float4*)d_out);
}